// round 13
// baseline (speedup 1.0000x reference)
#include <cuda_runtime.h>
#include <cuda_bf16.h>

// NLL closed form for V = sig2e*I + sig2b*Z Z^T (block-diagonal per group):
//   logdet V   = N*log(sig2e) + sum_{g:n_g>0} [log(sig2e + n_g*sig2b) - log(sig2e)]
//   r^T V^-1 r = (1/sig2e) * [ sum r_i^2 - sum_g sig2b*s_g^2/(sig2e+n_g*sig2b) ]
//
// CONVERGED KERNEL (best measured: ncu 6.59us, wall 8.704us = T_ovh floor +
// replay overhead; explicit work chain is ~1.5us equivalent).
//
// Structure: 8 CTAs x 512 threads, 1 elem/thread.
//  - one packed 64-bit REDG per element into an L2-resident histogram:
//    count in bits[46:64), biased fixed-point residual sum in bits[0:46)
//    (u = round(r*2^26) + 2^32 > 0 always; group sum < 2^45 -> never carries
//    into the count field; decode subtracts n*2^32). Exact, order-independent,
//    deterministic.
//  - sum of squares: fp32 warp shuffle tree + one integer REDG per warp.
//  - bar.sync then ONE acq_rel ticket atomic per CTA: bar gives intra-CTA
//    happens-before, the release publishes this CTA's REDGs, the winner's
//    acquire makes all peers' visible. Winner = last ticket, no spin.
//  - winner: g_ss_fx -> smem + scratch resets issued FIRST (latency overlaps
//    bin decode), log(sig2e) precomputed before the ticket, 1000 bins as two
//    back-to-back independent loads per thread (one L2 round), fp32
//    shuffle-tree reduce, single STG.
//  - all __device__ scratch is re-zeroed by the winner so every graph replay
//    starts from the load-time-zero invariant.

#define N_ELEMS    4096
#define NUM_GROUPS 1000
#define LOG_2PI    1.8378770664093453
#define NCTAS      8
#define NTHREADS   512

#define FX_SCALE   67108864.0f            // 2^26
#define FX_INV_F   (1.0f / 67108864.0f)
#define FX_INV_D   (1.0 / 67108864.0)
#define SUM_BITS   46
#define MASK46     ((1ULL << SUM_BITS) - 1ULL)
#define CNT_ONE    (1ULL << SUM_BITS)
#define BIAS       (1LL << 32)

__device__ unsigned long long g_hist[NUM_GROUPS];
__device__ unsigned long long g_ss_fx;
__device__ unsigned int       g_done;

__global__ __launch_bounds__(NTHREADS, 1)
void nll_fused_kernel(const float* __restrict__ y_true,
                      const float* __restrict__ y_pred,
                      const int*   __restrict__ z_idx,
                      const float* __restrict__ p_sig2e,
                      const float* __restrict__ p_sig2b,
                      float* __restrict__ out)
{
    __shared__ float s_red[2][16];
    __shared__ unsigned long long s_ss;
    __shared__ int s_last;

    const int tid  = threadIdx.x;
    const int lane = tid & 31;
    const int wid  = tid >> 5;
    const int i    = blockIdx.x * NTHREADS + tid;

    // hoisted scalar loads + log: overlap the element pass, off the tail
    const float sig2e = __ldg(p_sig2e);
    const float sig2b = __ldg(p_sig2b);
    const float log_sig2e = __logf(sig2e);

    // ---- element pass: one packed REDG per element ----
    float r = y_true[i] - y_pred[i];
    int   g = z_idx[i];
    g = (g < 0) ? 0 : (g >= NUM_GROUPS ? NUM_GROUPS - 1 : g);

    long long u = llrintf(r * FX_SCALE) + BIAS;     // in (0, 2^33)
    atomicAdd(&g_hist[g], CNT_ONE + (unsigned long long)u);

    // sum of squares: warp shuffle + one integer RED per warp (deterministic)
    float ss = r * r;
    #pragma unroll
    for (int off = 16; off > 0; off >>= 1)
        ss += __shfl_down_sync(0xFFFFFFFFu, ss, off);
    if (lane == 0)
        atomicAdd(&g_ss_fx, (unsigned long long)llrintf(ss * FX_SCALE));

    // ---- ticket: bar.sync orders all CTA writes before tid0's release;
    //      the winner's acquire makes all peers' REDGs visible ----
    __syncthreads();
    if (tid == 0) {
        unsigned int old;
        asm volatile("atom.acq_rel.gpu.global.add.u32 %0, [%1], %2;"
                     : "=r"(old)
                     : "l"(&g_done), "r"(1u)
                     : "memory");
        s_last = (old == NCTAS - 1);
    }
    __syncthreads();
    if (!s_last) return;

    // ---- finish (winner CTA): ss load + resets issue first, overlap decode
    if (tid == 0) {
        s_ss    = g_ss_fx;     // latency hidden behind bin decode below
        g_ss_fx = 0ULL;
        g_done  = 0u;
    }

    // two independent bins per thread; both loads issue before either decode
    const int g0 = tid;
    const int g1 = tid + NTHREADS;
    unsigned long long h0 = g_hist[g0];
    unsigned long long h1 = (g1 < NUM_GROUPS) ? g_hist[g1] : 0ULL;
    g_hist[g0] = 0ULL;                              // restore for next replay
    if (g1 < NUM_GROUPS) g_hist[g1] = 0ULL;

    float v1 = 0.0f;   // sum_g [log(sig2e + n_g sig2b) - log(sig2e)]
    float v2 = 0.0f;   // sum_g sig2b * s_g^2 / (sig2e + n_g sig2b)

    {
        int       n0 = (int)(h0 >> SUM_BITS);
        long long s0 = (long long)(h0 & MASK46) - (long long)n0 * BIAS;
        if (n0 > 0) {
            float d = sig2e + (float)n0 * sig2b;
            float s = __ll2float_rn(s0) * FX_INV_F;
            v1 += __logf(d) - log_sig2e;
            v2 += __fdividef(sig2b * s * s, d);
        }
        int       n1 = (int)(h1 >> SUM_BITS);
        long long s1 = (long long)(h1 & MASK46) - (long long)n1 * BIAS;
        if (n1 > 0) {
            float d = sig2e + (float)n1 * sig2b;
            float s = __ll2float_rn(s1) * FX_INV_F;
            v1 += __logf(d) - log_sig2e;
            v2 += __fdividef(sig2b * s * s, d);
        }
    }

    // float block reduction: 16 warps -> smem -> warp 0
    #pragma unroll
    for (int off = 16; off > 0; off >>= 1) {
        v1 += __shfl_down_sync(0xFFFFFFFFu, v1, off);
        v2 += __shfl_down_sync(0xFFFFFFFFu, v2, off);
    }
    if (lane == 0) { s_red[0][wid] = v1; s_red[1][wid] = v2; }
    __syncthreads();
    if (wid == 0) {
        v1 = (lane < 16) ? s_red[0][lane] : 0.0f;
        v2 = (lane < 16) ? s_red[1][lane] : 0.0f;
        #pragma unroll
        for (int off = 8; off > 0; off >>= 1) {
            v1 += __shfl_down_sync(0xFFFFFFFFu, v1, off);
            v2 += __shfl_down_sync(0xFFFFFFFFu, v2, off);
        }
        if (lane == 0) {
            double ss_tot = (double)s_ss * FX_INV_D;   // smem, already resident
            double logdet = (double)N_ELEMS * (double)log_sig2e + (double)v1;
            double quad   = (ss_tot - (double)v2) / (double)sig2e;
            double total  = 0.5 * (double)N_ELEMS * LOG_2PI
                          + 0.5 * logdet
                          + 0.5 * quad;
            out[0] = (float)total;
        }
    }
}

extern "C" void kernel_launch(void* const* d_in, const int* in_sizes, int n_in,
                              void* d_out, int out_size)
{
    const float* y_true = (const float*)d_in[0];
    const float* y_pred = (const float*)d_in[1];
    const int*   z_idx  = (const int*)d_in[2];
    const float* sig2e  = (const float*)d_in[3];
    const float* sig2b  = (const float*)d_in[4];
    float*       out    = (float*)d_out;

    nll_fused_kernel<<<NCTAS, NTHREADS>>>(y_true, y_pred, z_idx, sig2e, sig2b, out);
}

// round 14
// speedup vs baseline: 1.0734x; 1.0734x over previous
#include <cuda_runtime.h>
#include <cuda_bf16.h>

// NLL closed form for V = sig2e*I + sig2b*Z Z^T (block-diagonal per group):
//   logdet V   = N*log(sig2e) + sum_{g:n_g>0} [log(sig2e + n_g*sig2b) - log(sig2e)]
//   r^T V^-1 r = (1/sig2e) * [ sum r_i^2 - sum_g sig2b*s_g^2/(sig2e+n_g*sig2b) ]
//
// CONVERGED KERNEL (best measured: ncu 6.59us, wall 8.70-8.90us; explicit
// work chain ~1.5us, remainder is T_ovh launch floor + graph-replay overhead).
//
// Structure: 8 CTAs x 512 threads, 1 elem/thread.
//  - one packed 64-bit REDG per element into an L2-resident histogram:
//    count in bits[46:64), biased fixed-point residual sum in bits[0:46)
//    (u = round(r*2^26) + 2^32 > 0 always; group sum < 2^45 -> never carries
//    into the count field; decode subtracts n*2^32). Exact, order-independent,
//    deterministic.
//  - sum of squares: fp32 warp shuffle tree + one integer REDG per warp.
//  - bar.sync then ONE acq_rel ticket atomic per CTA: bar gives intra-CTA
//    happens-before, the release publishes this CTA's REDGs, the winner's
//    acquire makes all peers' visible. Winner = last ticket, no spin.
//  - winner: g_ss_fx -> smem + scratch resets issued FIRST (latency overlaps
//    bin decode), log(sig2e) precomputed before the ticket, 1000 bins as two
//    back-to-back independent loads per thread (one L2 round), fp32
//    shuffle-tree reduce, single STG.
//  - all __device__ scratch is re-zeroed by the winner so every graph replay
//    starts from the load-time-zero invariant.
//
// Rejected on cycle model (see session journal): single-CTA (4096 REDG lanes
// on one LSU ~ 3.5k cyc >> ticket cost), 16x256 (ticket fan-in), 2-kernel
// split (measured 12.4us), smem atomics (measured 14.5us), match_any
// pre-aggregation (no contention to remove at 4096/1000 occupancy).

#define N_ELEMS    4096
#define NUM_GROUPS 1000
#define LOG_2PI    1.8378770664093453
#define NCTAS      8
#define NTHREADS   512

#define FX_SCALE   67108864.0f            // 2^26
#define FX_INV_F   (1.0f / 67108864.0f)
#define FX_INV_D   (1.0 / 67108864.0)
#define SUM_BITS   46
#define MASK46     ((1ULL << SUM_BITS) - 1ULL)
#define CNT_ONE    (1ULL << SUM_BITS)
#define BIAS       (1LL << 32)

__device__ unsigned long long g_hist[NUM_GROUPS];
__device__ unsigned long long g_ss_fx;
__device__ unsigned int       g_done;

__global__ __launch_bounds__(NTHREADS, 1)
void nll_fused_kernel(const float* __restrict__ y_true,
                      const float* __restrict__ y_pred,
                      const int*   __restrict__ z_idx,
                      const float* __restrict__ p_sig2e,
                      const float* __restrict__ p_sig2b,
                      float* __restrict__ out)
{
    __shared__ float s_red[2][16];
    __shared__ unsigned long long s_ss;
    __shared__ int s_last;

    const int tid  = threadIdx.x;
    const int lane = tid & 31;
    const int wid  = tid >> 5;
    const int i    = blockIdx.x * NTHREADS + tid;

    // hoisted scalar loads + log: overlap the element pass, off the tail
    const float sig2e = __ldg(p_sig2e);
    const float sig2b = __ldg(p_sig2b);
    const float log_sig2e = __logf(sig2e);

    // ---- element pass: one packed REDG per element ----
    float r = y_true[i] - y_pred[i];
    int   g = z_idx[i];
    g = (g < 0) ? 0 : (g >= NUM_GROUPS ? NUM_GROUPS - 1 : g);

    long long u = llrintf(r * FX_SCALE) + BIAS;     // in (0, 2^33)
    atomicAdd(&g_hist[g], CNT_ONE + (unsigned long long)u);

    // sum of squares: warp shuffle + one integer RED per warp (deterministic)
    float ss = r * r;
    #pragma unroll
    for (int off = 16; off > 0; off >>= 1)
        ss += __shfl_down_sync(0xFFFFFFFFu, ss, off);
    if (lane == 0)
        atomicAdd(&g_ss_fx, (unsigned long long)llrintf(ss * FX_SCALE));

    // ---- ticket: bar.sync orders all CTA writes before tid0's release;
    //      the winner's acquire makes all peers' REDGs visible ----
    __syncthreads();
    if (tid == 0) {
        unsigned int old;
        asm volatile("atom.acq_rel.gpu.global.add.u32 %0, [%1], %2;"
                     : "=r"(old)
                     : "l"(&g_done), "r"(1u)
                     : "memory");
        s_last = (old == NCTAS - 1);
    }
    __syncthreads();
    if (!s_last) return;

    // ---- finish (winner CTA): ss load + resets issue first, overlap decode
    if (tid == 0) {
        s_ss    = g_ss_fx;     // latency hidden behind bin decode below
        g_ss_fx = 0ULL;
        g_done  = 0u;
    }

    // two independent bins per thread; both loads issue before either decode
    const int g0 = tid;
    const int g1 = tid + NTHREADS;
    unsigned long long h0 = g_hist[g0];
    unsigned long long h1 = (g1 < NUM_GROUPS) ? g_hist[g1] : 0ULL;
    g_hist[g0] = 0ULL;                              // restore for next replay
    if (g1 < NUM_GROUPS) g_hist[g1] = 0ULL;

    float v1 = 0.0f;   // sum_g [log(sig2e + n_g sig2b) - log(sig2e)]
    float v2 = 0.0f;   // sum_g sig2b * s_g^2 / (sig2e + n_g sig2b)

    {
        int       n0 = (int)(h0 >> SUM_BITS);
        long long s0 = (long long)(h0 & MASK46) - (long long)n0 * BIAS;
        if (n0 > 0) {
            float d = sig2e + (float)n0 * sig2b;
            float s = __ll2float_rn(s0) * FX_INV_F;
            v1 += __logf(d) - log_sig2e;
            v2 += __fdividef(sig2b * s * s, d);
        }
        int       n1 = (int)(h1 >> SUM_BITS);
        long long s1 = (long long)(h1 & MASK46) - (long long)n1 * BIAS;
        if (n1 > 0) {
            float d = sig2e + (float)n1 * sig2b;
            float s = __ll2float_rn(s1) * FX_INV_F;
            v1 += __logf(d) - log_sig2e;
            v2 += __fdividef(sig2b * s * s, d);
        }
    }

    // float block reduction: 16 warps -> smem -> warp 0
    #pragma unroll
    for (int off = 16; off > 0; off >>= 1) {
        v1 += __shfl_down_sync(0xFFFFFFFFu, v1, off);
        v2 += __shfl_down_sync(0xFFFFFFFFu, v2, off);
    }
    if (lane == 0) { s_red[0][wid] = v1; s_red[1][wid] = v2; }
    __syncthreads();
    if (wid == 0) {
        v1 = (lane < 16) ? s_red[0][lane] : 0.0f;
        v2 = (lane < 16) ? s_red[1][lane] : 0.0f;
        #pragma unroll
        for (int off = 8; off > 0; off >>= 1) {
            v1 += __shfl_down_sync(0xFFFFFFFFu, v1, off);
            v2 += __shfl_down_sync(0xFFFFFFFFu, v2, off);
        }
        if (lane == 0) {
            double ss_tot = (double)s_ss * FX_INV_D;   // smem, already resident
            double logdet = (double)N_ELEMS * (double)log_sig2e + (double)v1;
            double quad   = (ss_tot - (double)v2) / (double)sig2e;
            double total  = 0.5 * (double)N_ELEMS * LOG_2PI
                          + 0.5 * logdet
                          + 0.5 * quad;
            out[0] = (float)total;
        }
    }
}

extern "C" void kernel_launch(void* const* d_in, const int* in_sizes, int n_in,
                              void* d_out, int out_size)
{
    const float* y_true = (const float*)d_in[0];
    const float* y_pred = (const float*)d_in[1];
    const int*   z_idx  = (const int*)d_in[2];
    const float* sig2e  = (const float*)d_in[3];
    const float* sig2b  = (const float*)d_in[4];
    float*       out    = (float*)d_out;

    nll_fused_kernel<<<NCTAS, NTHREADS>>>(y_true, y_pred, z_idx, sig2e, sig2b, out);
}